// round 3
// baseline (speedup 1.0000x reference)
#include <cuda_runtime.h>

// Problem constants
#define C_DIM 256
#define HID_DIM 256
#define HW_DIM 16384          // 128*128
#define NT 64                 // pixel tile per CTA
#define KC 32                 // K chunk
#define XP 68                 // smem row pitch (floats) for X/H tiles (pad vs 64)

// mask encoding mode: 0 = int32, 1 = float32, 2 = uint8 (packed bytes)
__device__ int g_mask_mode;

// ---- packed f32x2 helpers (Blackwell sm_103a) ----
__device__ __forceinline__ unsigned long long pack2(float lo, float hi) {
    unsigned long long r;
    asm("mov.b64 %0, {%1, %2};" : "=l"(r) : "f"(lo), "f"(hi));
    return r;
}
__device__ __forceinline__ void unpack2(unsigned long long v, float& lo, float& hi) {
    asm("mov.b64 {%0, %1}, %2;" : "=f"(lo), "=f"(hi) : "l"(v));
}
__device__ __forceinline__ unsigned long long fma2(unsigned long long a,
                                                   unsigned long long b,
                                                   unsigned long long c) {
    unsigned long long d;
    asm("fma.rn.f32x2 %0, %1, %2, %3;" : "=l"(d) : "l"(a), "l"(b), "l"(c));
    return d;
}

// Detect how the boolean mask was materialized by the harness.
// Scans the first 65536 32-bit words — safe under all three interpretations
// (uint8 buffer = 65536 words, int32/float32 buffers = 262144 words).
extern "C" __global__ void detect_mask_mode_kernel(const unsigned int* __restrict__ m)
{
    __shared__ int s_float, s_bytes;
    if (threadIdx.x == 0) { s_float = 0; s_bytes = 0; }
    __syncthreads();

    int saw_float = 0, saw_bytes = 0;
    for (int i = threadIdx.x; i < 65536; i += blockDim.x) {
        unsigned int w = m[i];
        if (w == 0x3F800000u) saw_float = 1;
        else if (w > 1u)      saw_bytes = 1;   // packed uint8 bools (e.g. 0x00010001)
    }
    if (saw_float) atomicOr(&s_float, 1);
    if (saw_bytes) atomicOr(&s_bytes, 1);
    __syncthreads();
    if (threadIdx.x == 0) {
        int mode = 0;                 // default: int32 (values 0/1 only)
        if (s_float) mode = 1;        // float32
        else if (s_bytes) mode = 2;   // uint8
        g_mask_mode = mode;
    }
}

// Fused masked MLP over a 64-pixel tile of one batch.
//  H = relu(W1^T X + b1) ; Z = W2^T H + b2 ; out = mask ? Z : X
extern "C" __global__ void __launch_bounds__(256, 1)
fused_mlp_kernel(const float* __restrict__ x,
                 const void* __restrict__ mask,
                 const float* __restrict__ W1,
                 const float* __restrict__ b1,
                 const float* __restrict__ W2,
                 const float* __restrict__ b2,
                 float* __restrict__ out)
{
    extern __shared__ float smem[];
    float* Xs = smem;                       // [256][XP]
    float* Hs = Xs + 256 * XP;              // [256][XP]
    float* Ws = Hs + 256 * XP;              // [KC][256]
    unsigned char* msk = (unsigned char*)(Ws + KC * 256);  // [64]

    const int tid = threadIdx.x;
    const int blk = blockIdx.x;
    const int b   = blk >> 8;               // batch (16)
    const int p0  = (blk & 255) * NT;       // pixel tile start within HW

    const float* xb = x + (size_t)b * C_DIM * HW_DIM + p0;

    if (tid < NT) {
        int gi = b * HW_DIM + p0 + tid;
        int mode = g_mask_mode;
        int mv;
        if (mode == 0)      mv = (((const int*)mask)[gi] != 0);
        else if (mode == 1) mv = (((const float*)mask)[gi] != 0.0f);
        else                mv = (((const unsigned char*)mask)[gi] != 0);
        msk[tid] = (unsigned char)mv;
    }

    // Load X tile: 256 rows x 64 cols (float4 coalesced)
    #pragma unroll
    for (int i = 0; i < 16; i++) {
        int idx4 = tid + i * 256;           // 0..4095
        int c  = idx4 >> 4;                 // /16
        int p4 = idx4 & 15;
        float4 v = *(const float4*)(xb + (size_t)c * HW_DIM + p4 * 4);
        *(float4*)(Xs + c * XP + p4 * 4) = v;
    }

    const int tm = tid >> 3;                // 0..31  -> 8 M rows
    const int tn = tid & 7;                 // 0..7   -> 8 N cols (4 f32x2 pairs)

    unsigned long long acc[8][4];

    #pragma unroll 1
    for (int stage = 0; stage < 2; stage++) {
        const float* Wg   = stage ? W2 : W1;
        const float* Bsm  = stage ? Hs : Xs;
        const float* bias = stage ? b2 : b1;

        #pragma unroll
        for (int i = 0; i < 8; i++)
            #pragma unroll
            for (int j = 0; j < 4; j++)
                acc[i][j] = 0ull;

        #pragma unroll 1
        for (int kc = 0; kc < (C_DIM / KC); kc++) {
            __syncthreads();
            // Load weight chunk: rows kc*32 .. +31, 256 cols
            #pragma unroll
            for (int i = 0; i < 8; i++) {
                int idx4 = tid + i * 256;   // 0..2047
                int r  = idx4 >> 6;         // 0..31
                int d4 = idx4 & 63;         // 0..63
                *(float4*)(Ws + r * 256 + d4 * 4) =
                    *(const float4*)(Wg + ((size_t)(kc * KC + r)) * 256 + d4 * 4);
            }
            __syncthreads();

            #pragma unroll 4
            for (int k = 0; k < KC; k++) {
                // FIX: activation row must track the K-chunk (kc*KC + k), matching
                // the weight rows loaded above. Previously read channels 0..31 only.
                const float* brow = Bsm + (kc * KC + k) * XP + tn * 8;
                ulonglong2 b01 = *(const ulonglong2*)(brow);
                ulonglong2 b23 = *(const ulonglong2*)(brow + 4);
                unsigned long long bb[4] = { b01.x, b01.y, b23.x, b23.y };

                float4 w0 = *(const float4*)(Ws + k * 256 + tm * 8);
                float4 w1 = *(const float4*)(Ws + k * 256 + tm * 8 + 4);
                unsigned long long a[8];
                a[0] = pack2(w0.x, w0.x); a[1] = pack2(w0.y, w0.y);
                a[2] = pack2(w0.z, w0.z); a[3] = pack2(w0.w, w0.w);
                a[4] = pack2(w1.x, w1.x); a[5] = pack2(w1.y, w1.y);
                a[6] = pack2(w1.z, w1.z); a[7] = pack2(w1.w, w1.w);

                #pragma unroll
                for (int i = 0; i < 8; i++)
                    #pragma unroll
                    for (int j = 0; j < 4; j++)
                        acc[i][j] = fma2(a[i], bb[j], acc[i][j]);
            }
        }

        // Epilogue: bias (+relu for stage 0), write to Hs.
        // Sync first: in stage 1 other threads may still be reading Hs.
        __syncthreads();
        #pragma unroll
        for (int i = 0; i < 8; i++) {
            float bv = bias[tm * 8 + i];
            float* hrow = Hs + (tm * 8 + i) * XP + tn * 8;
            #pragma unroll
            for (int j = 0; j < 4; j++) {
                float lo, hi;
                unpack2(acc[i][j], lo, hi);
                lo += bv; hi += bv;
                if (stage == 0) { lo = fmaxf(lo, 0.f); hi = fmaxf(hi, 0.f); }
                hrow[2 * j]     = lo;
                hrow[2 * j + 1] = hi;
            }
        }
        __syncthreads();
    }

    // Write out: out = mask ? Z(=Hs) : X(=Xs), float4 coalesced
    float* ob = out + (size_t)b * C_DIM * HW_DIM + p0;
    #pragma unroll
    for (int i = 0; i < 16; i++) {
        int idx4 = tid + i * 256;
        int c  = idx4 >> 4;
        int p4 = idx4 & 15;
        float4 zv = *(const float4*)(Hs + c * XP + p4 * 4);
        float4 xv = *(const float4*)(Xs + c * XP + p4 * 4);
        float4 o;
        o.x = msk[p4 * 4 + 0] ? zv.x : xv.x;
        o.y = msk[p4 * 4 + 1] ? zv.y : xv.y;
        o.z = msk[p4 * 4 + 2] ? zv.z : xv.z;
        o.w = msk[p4 * 4 + 3] ? zv.w : xv.w;
        *(float4*)(ob + (size_t)c * HW_DIM + p4 * 4) = o;
    }
}

extern "C" void kernel_launch(void* const* d_in, const int* in_sizes, int n_in,
                              void* d_out, int out_size)
{
    const float* x    = (const float*)d_in[0];
    const void*  mask = d_in[1];
    const float* W1   = (const float*)d_in[2];
    const float* b1   = (const float*)d_in[3];
    const float* W2   = (const float*)d_in[4];
    const float* b2   = (const float*)d_in[5];
    float*       out  = (float*)d_out;

    detect_mask_mode_kernel<<<1, 256>>>((const unsigned int*)mask);

    const int smem_bytes = (2 * 256 * XP + KC * 256) * (int)sizeof(float) + 64;
    cudaFuncSetAttribute(fused_mlp_kernel,
                         cudaFuncAttributeMaxDynamicSharedMemorySize, smem_bytes);

    // 16 batches * (16384/64) pixel tiles = 4096 CTAs
    fused_mlp_kernel<<<4096, 256, smem_bytes>>>(x, mask, W1, b1, W2, b2, out);
}

// round 4
// speedup vs baseline: 2.4748x; 2.4748x over previous
#include <cuda_runtime.h>
#include <cuda_bf16.h>
#include <cstdint>

#define C_DIM 256
#define HW_DIM 16384
#define P_TILE 128
#define XPITCH 136   // bf16 elems per X/H smem row (128 + 8 pad)
#define WPITCH 72    // bf16 elems per W smem row  (64 + 8 pad)

// mask encoding mode: 0 = int32, 1 = float32, 2 = uint8 (packed bytes)
__device__ int g_mask_mode;

// Pre-split, pre-transposed weights (bf16 hi/lo). W1T[d][c] = W1[c][d]; W2T[co][d] = W2[d][co].
__device__ __align__(16) __nv_bfloat16 g_W1T_hi[65536];
__device__ __align__(16) __nv_bfloat16 g_W1T_lo[65536];
__device__ __align__(16) __nv_bfloat16 g_W2T_hi[65536];
__device__ __align__(16) __nv_bfloat16 g_W2T_lo[65536];

// ---------------- mask dtype detection (validated in R3) ----------------
extern "C" __global__ void detect_mask_mode_kernel(const unsigned int* __restrict__ m)
{
    __shared__ int s_float, s_bytes;
    if (threadIdx.x == 0) { s_float = 0; s_bytes = 0; }
    __syncthreads();
    int saw_float = 0, saw_bytes = 0;
    for (int i = threadIdx.x; i < 65536; i += blockDim.x) {
        unsigned int w = m[i];
        if (w == 0x3F800000u) saw_float = 1;
        else if (w > 1u)      saw_bytes = 1;
    }
    if (saw_float) atomicOr(&s_float, 1);
    if (saw_bytes) atomicOr(&s_bytes, 1);
    __syncthreads();
    if (threadIdx.x == 0) {
        int mode = 0;
        if (s_float) mode = 1;
        else if (s_bytes) mode = 2;
        g_mask_mode = mode;
    }
}

// ---------------- weight prep: transpose + bf16 hi/lo split ----------------
extern "C" __global__ void prep_weights_kernel(const float* __restrict__ W1,
                                               const float* __restrict__ W2)
{
    int e = blockIdx.x * 256 + threadIdx.x;   // 0..65535
    int r = e >> 8;      // output row (d for W1T, c_out for W2T)
    int q = e & 255;     // output col (c for W1T, d for W2T)

    float w1 = W1[q * 256 + r];
    __nv_bfloat16 h1 = __float2bfloat16(w1);
    g_W1T_hi[e] = h1;
    g_W1T_lo[e] = __float2bfloat16(w1 - __bfloat162float(h1));

    float w2 = W2[q * 256 + r];
    __nv_bfloat16 h2 = __float2bfloat16(w2);
    g_W2T_hi[e] = h2;
    g_W2T_lo[e] = __float2bfloat16(w2 - __bfloat162float(h2));
}

// ---------------- ldmatrix / mma helpers ----------------
__device__ __forceinline__ uint32_t smem_u32(const void* p) {
    return (uint32_t)__cvta_generic_to_shared(p);
}
__device__ __forceinline__ void ldsm_x4(uint32_t* r, uint32_t addr) {
    asm volatile("ldmatrix.sync.aligned.m8n8.x4.shared.b16 {%0,%1,%2,%3}, [%4];"
                 : "=r"(r[0]), "=r"(r[1]), "=r"(r[2]), "=r"(r[3]) : "r"(addr));
}
__device__ __forceinline__ void ldsm_x4_t(uint32_t* r, uint32_t addr) {
    asm volatile("ldmatrix.sync.aligned.m8n8.x4.trans.shared.b16 {%0,%1,%2,%3}, [%4];"
                 : "=r"(r[0]), "=r"(r[1]), "=r"(r[2]), "=r"(r[3]) : "r"(addr));
}
__device__ __forceinline__ void mma_16816(float* d, const uint32_t* a, const uint32_t* b) {
    asm volatile("mma.sync.aligned.m16n8k16.row.col.f32.bf16.bf16.f32 "
                 "{%0,%1,%2,%3}, {%4,%5,%6,%7}, {%8,%9}, {%0,%1,%2,%3};"
                 : "+f"(d[0]), "+f"(d[1]), "+f"(d[2]), "+f"(d[3])
                 : "r"(a[0]), "r"(a[1]), "r"(a[2]), "r"(a[3]), "r"(b[0]), "r"(b[1]));
}

// One GEMM: acc[m=out-chan][n=pixel] += sum_k WT[m][k] * B[k][n]
// WT (hi/lo) streamed from gmem in 64-wide K chunks into Wh/Wl smem;
// B (hi/lo) fully resident in Bh/Bl smem ([k][n], pitch XPITCH).
// 3 passes: (Wh,Bh), (Wh,Bl), (Wl,Bh).
__device__ __forceinline__ void gemm_256(const __nv_bfloat16* __restrict__ WThi_g,
                                         const __nv_bfloat16* __restrict__ WTlo_g,
                                         __nv_bfloat16* Wh, __nv_bfloat16* Wl,
                                         const __nv_bfloat16* Bh, const __nv_bfloat16* Bl,
                                         float acc[4][8][4],
                                         int tid, int wd, int wp, int lane)
{
    const int l15 = lane & 15;
    const int l16 = (lane >> 4) * 8;

    #pragma unroll 1
    for (int kc = 0; kc < 4; kc++) {
        __syncthreads();
        #pragma unroll
        for (int t = 0; t < 8; t++) {
            int idx = tid + t * 256;          // 0..2047
            int d  = idx >> 3;
            int c8 = (idx & 7) * 8;
            *(uint4*)(Wh + d * WPITCH + c8) =
                *(const uint4*)(WThi_g + (size_t)d * 256 + kc * 64 + c8);
            *(uint4*)(Wl + d * WPITCH + c8) =
                *(const uint4*)(WTlo_g + (size_t)d * 256 + kc * 64 + c8);
        }
        __syncthreads();

        #pragma unroll 1
        for (int pass = 0; pass < 3; pass++) {
            const __nv_bfloat16* Asm = (pass == 2) ? Wl : Wh;
            const __nv_bfloat16* Bsm = (pass == 1) ? Bl : Bh;

            #pragma unroll
            for (int ks = 0; ks < 4; ks++) {
                const int ka = ks * 16;            // k within W chunk
                const int kb = kc * 64 + ks * 16;  // global k within B

                uint32_t afr[4][4];
                #pragma unroll
                for (int i = 0; i < 4; i++)
                    ldsm_x4(afr[i], smem_u32(Asm + (wd * 64 + i * 16 + l15) * WPITCH + ka + l16));

                uint32_t bfr[4][4];
                #pragma unroll
                for (int jj = 0; jj < 4; jj++)
                    ldsm_x4_t(bfr[jj], smem_u32(Bsm + (kb + l15) * XPITCH + wp * 64 + jj * 16 + l16));

                #pragma unroll
                for (int i = 0; i < 4; i++)
                    #pragma unroll
                    for (int j = 0; j < 8; j++)
                        mma_16816(acc[i][j], afr[i], &bfr[j >> 1][(j & 1) * 2]);
            }
        }
    }
}

// ---------------- fused masked MLP, tensor-core version ----------------
extern "C" __global__ void __launch_bounds__(256, 1)
mlp_mma_kernel(const float* __restrict__ x,
               const void* __restrict__ mask,
               const float* __restrict__ b1,
               const float* __restrict__ b2,
               float* __restrict__ out)
{
    extern __shared__ __nv_bfloat16 sm[];
    __nv_bfloat16* Xh = sm;                 // [256][XPITCH]   (aliased as H_hi after GEMM1)
    __nv_bfloat16* Xl = sm + 34816;         // [256][XPITCH]   (aliased as H_lo)
    __nv_bfloat16* Wh = sm + 69632;         // [256][WPITCH]
    __nv_bfloat16* Wl = sm + 88064;         // [256][WPITCH]
    unsigned char* msk = (unsigned char*)(sm + 106496);   // [128]

    const int tid  = threadIdx.x;
    const int lane = tid & 31;
    const int w    = tid >> 5;
    const int wd   = w >> 1;                // 0..3 -> out-channel quadrant (64)
    const int wp   = w & 1;                 // 0..1 -> pixel half (64)
    const int g    = lane >> 2;
    const int tc   = lane & 3;

    const int b  = blockIdx.x >> 7;               // batch
    const int p0 = (blockIdx.x & 127) * P_TILE;   // pixel tile start

    // mask
    if (tid < P_TILE) {
        int gi = b * HW_DIM + p0 + tid;
        int mode = g_mask_mode, mv;
        if (mode == 0)      mv = (((const int*)mask)[gi] != 0);
        else if (mode == 1) mv = (((const float*)mask)[gi] != 0.0f);
        else                mv = (((const unsigned char*)mask)[gi] != 0);
        msk[tid] = (unsigned char)mv;
    }

    // load X [256 c][128 p] fp32 -> split into Xh/Xl bf16 (layout [c][p])
    const float* xb = x + (size_t)b * C_DIM * HW_DIM + p0;
    #pragma unroll
    for (int it = 0; it < 32; it++) {
        int idx = tid + it * 256;        // 0..8191 float4s
        int c = idx >> 5;                // 32 float4 per row
        int q = (idx & 31) * 4;
        float4 v = *(const float4*)(xb + (size_t)c * HW_DIM + q);
        __nv_bfloat16 h0 = __float2bfloat16(v.x), h1 = __float2bfloat16(v.y);
        __nv_bfloat16 h2 = __float2bfloat16(v.z), h3 = __float2bfloat16(v.w);
        __nv_bfloat162 hA = __nv_bfloat162(h0, h1), hB = __nv_bfloat162(h2, h3);
        __nv_bfloat162 lA = __nv_bfloat162(__float2bfloat16(v.x - __bfloat162float(h0)),
                                           __float2bfloat16(v.y - __bfloat162float(h1)));
        __nv_bfloat162 lB = __nv_bfloat162(__float2bfloat16(v.z - __bfloat162float(h2)),
                                           __float2bfloat16(v.w - __bfloat162float(h3)));
        *(__nv_bfloat162*)(Xh + c * XPITCH + q)     = hA;
        *(__nv_bfloat162*)(Xh + c * XPITCH + q + 2) = hB;
        *(__nv_bfloat162*)(Xl + c * XPITCH + q)     = lA;
        *(__nv_bfloat162*)(Xl + c * XPITCH + q + 2) = lB;
    }
    __syncthreads();

    float acc[4][8][4];

    // ---- GEMM1: H = relu(W1T @ X + b1) ----
    #pragma unroll
    for (int i = 0; i < 4; i++)
        #pragma unroll
        for (int j = 0; j < 8; j++)
            #pragma unroll
            for (int r = 0; r < 4; r++) acc[i][j][r] = 0.f;

    gemm_256(g_W1T_hi, g_W1T_lo, Wh, Wl, Xh, Xl, acc, tid, wd, wp, lane);

    __syncthreads();   // everyone done reading Xh/Xl
    #pragma unroll
    for (int i = 0; i < 4; i++) {
        int d0 = wd * 64 + i * 16 + g;
        float bv0 = b1[d0], bv1 = b1[d0 + 8];
        #pragma unroll
        for (int j = 0; j < 8; j++) {
            int p = wp * 64 + j * 8 + tc * 2;
            float h00 = fmaxf(acc[i][j][0] + bv0, 0.f);
            float h01 = fmaxf(acc[i][j][1] + bv0, 0.f);
            float h10 = fmaxf(acc[i][j][2] + bv1, 0.f);
            float h11 = fmaxf(acc[i][j][3] + bv1, 0.f);
            __nv_bfloat16 a0 = __float2bfloat16(h00), a1 = __float2bfloat16(h01);
            __nv_bfloat16 c0 = __float2bfloat16(h10), c1 = __float2bfloat16(h11);
            *(__nv_bfloat162*)(Xh + d0 * XPITCH + p) = __nv_bfloat162(a0, a1);
            *(__nv_bfloat162*)(Xl + d0 * XPITCH + p) =
                __nv_bfloat162(__float2bfloat16(h00 - __bfloat162float(a0)),
                               __float2bfloat16(h01 - __bfloat162float(a1)));
            *(__nv_bfloat162*)(Xh + (d0 + 8) * XPITCH + p) = __nv_bfloat162(c0, c1);
            *(__nv_bfloat162*)(Xl + (d0 + 8) * XPITCH + p) =
                __nv_bfloat162(__float2bfloat16(h10 - __bfloat162float(c0)),
                               __float2bfloat16(h11 - __bfloat162float(c1)));
        }
    }

    // ---- GEMM2: Y = W2T @ H + b2 ----
    #pragma unroll
    for (int i = 0; i < 4; i++)
        #pragma unroll
        for (int j = 0; j < 8; j++)
            #pragma unroll
            for (int r = 0; r < 4; r++) acc[i][j][r] = 0.f;

    gemm_256(g_W2T_hi, g_W2T_lo, Wh, Wl, Xh, Xl, acc, tid, wd, wp, lane);

    // ---- epilogue: out = mask ? y : x ----
    float* ob = out + (size_t)b * C_DIM * HW_DIM + p0;
    #pragma unroll
    for (int i = 0; i < 4; i++) {
        int c0 = wd * 64 + i * 16 + g;
        float bv0 = b2[c0], bv1 = b2[c0 + 8];
        #pragma unroll
        for (int j = 0; j < 8; j++) {
            int pl = wp * 64 + j * 8 + tc * 2;
            bool m0 = msk[pl], m1 = msk[pl + 1];
            float2 xv0 = *(const float2*)(xb + (size_t)c0 * HW_DIM + pl);
            float2 xv1 = *(const float2*)(xb + (size_t)(c0 + 8) * HW_DIM + pl);
            float2 o0, o1;
            o0.x = m0 ? acc[i][j][0] + bv0 : xv0.x;
            o0.y = m1 ? acc[i][j][1] + bv0 : xv0.y;
            o1.x = m0 ? acc[i][j][2] + bv1 : xv1.x;
            o1.y = m1 ? acc[i][j][3] + bv1 : xv1.y;
            *(float2*)(ob + (size_t)c0 * HW_DIM + pl)       = o0;
            *(float2*)(ob + (size_t)(c0 + 8) * HW_DIM + pl) = o1;
        }
    }
}

extern "C" void kernel_launch(void* const* d_in, const int* in_sizes, int n_in,
                              void* d_out, int out_size)
{
    const float* x    = (const float*)d_in[0];
    const void*  mask = d_in[1];
    const float* W1   = (const float*)d_in[2];
    const float* b1   = (const float*)d_in[3];
    const float* W2   = (const float*)d_in[4];
    const float* b2   = (const float*)d_in[5];
    float*       out  = (float*)d_out;

    detect_mask_mode_kernel<<<1, 256>>>((const unsigned int*)mask);
    prep_weights_kernel<<<256, 256>>>(W1, W2);

    const int smem_bytes = 106496 * 2 + 128;   // 213,120 B
    cudaFuncSetAttribute(mlp_mma_kernel,
                         cudaFuncAttributeMaxDynamicSharedMemorySize, smem_bytes);

    // 16 batches * 128 pixel tiles = 2048 CTAs
    mlp_mma_kernel<<<2048, 256, smem_bytes>>>(x, mask, b1, b2, out);
}

// round 6
// speedup vs baseline: 2.5269x; 1.0211x over previous
#include <cuda_runtime.h>
#include <cuda_bf16.h>
#include <cstdint>

#define HW 16384
#define BPITCH 136    // B smem pitch (bf16 elems): 256 ch rows x up to 128 px
#define WPITCH 40     // W smem pitch (bf16 elems) per 32-k chunk
#define NCHUNK 8      // 8 chunks of k=32
#define CHUNK_B 40960 // bytes per chunk (hi 20480 + lo 20480)
#define CHUNK_E 20480 // bf16 elems per chunk

// ---- smem layout (bytes) ----
#define SM_BH   0
#define SM_BL   69632
#define SM_W    139264            // 2 x 40960 ping-pong
#define SM_MSK  221184            // 128 bytes
#define SM_POS4 221312            // 32 x int16 (pos at 4-px granularity)
#define SM_IDX  221440            // 128 x int16
#define SM_FLG  221696            // ints: [0]=mode, [1]=nc
#define SM_TOTAL 221824

__device__ __align__(16) __nv_bfloat16 g_W1s[NCHUNK * CHUNK_E];
__device__ __align__(16) __nv_bfloat16 g_W2s[NCHUNK * CHUNK_E];

// ---------------- weight prep: transpose + hi/lo split + chunked padded layout ----------------
extern "C" __global__ void prep_weights_kernel(const float* __restrict__ W1,
                                               const float* __restrict__ W2)
{
    int k = blockIdx.x;      // 0..255 (input channel of WT's K dim)
    int m = threadIdx.x;     // 0..255 (output channel)
    int ch = k >> 5, kk = k & 31;
    int hi_off = ch * CHUNK_E + m * WPITCH + kk;

    float w1 = W1[k * 256 + m];                 // WT1[m][k] = W1[k][m]
    __nv_bfloat16 h1 = __float2bfloat16(w1);
    g_W1s[hi_off]         = h1;
    g_W1s[hi_off + 10240] = __float2bfloat16(w1 - __bfloat162float(h1));

    float w2 = W2[k * 256 + m];
    __nv_bfloat16 h2 = __float2bfloat16(w2);
    g_W2s[hi_off]         = h2;
    g_W2s[hi_off + 10240] = __float2bfloat16(w2 - __bfloat162float(h2));
}

// ---------------- ldmatrix / mma / cp.async helpers ----------------
__device__ __forceinline__ uint32_t smem_u32(const void* p) {
    return (uint32_t)__cvta_generic_to_shared(p);
}
__device__ __forceinline__ void ldsm_x4(uint32_t* r, uint32_t addr) {
    asm volatile("ldmatrix.sync.aligned.m8n8.x4.shared.b16 {%0,%1,%2,%3}, [%4];"
                 : "=r"(r[0]), "=r"(r[1]), "=r"(r[2]), "=r"(r[3]) : "r"(addr));
}
__device__ __forceinline__ void ldsm_x4_t(uint32_t* r, uint32_t addr) {
    asm volatile("ldmatrix.sync.aligned.m8n8.x4.trans.shared.b16 {%0,%1,%2,%3}, [%4];"
                 : "=r"(r[0]), "=r"(r[1]), "=r"(r[2]), "=r"(r[3]) : "r"(addr));
}
__device__ __forceinline__ void mma_16816(float* d, const uint32_t* a, const uint32_t* b) {
    asm volatile("mma.sync.aligned.m16n8k16.row.col.f32.bf16.bf16.f32 "
                 "{%0,%1,%2,%3}, {%4,%5,%6,%7}, {%8,%9}, {%0,%1,%2,%3};"
                 : "+f"(d[0]), "+f"(d[1]), "+f"(d[2]), "+f"(d[3])
                 : "r"(a[0]), "r"(a[1]), "r"(a[2]), "r"(a[3]), "r"(b[0]), "r"(b[1]));
}
__device__ __forceinline__ void cp16(uint32_t dst, const void* src) {
    asm volatile("cp.async.cg.shared.global [%0], [%1], 16;" :: "r"(dst), "l"(src));
}
__device__ __forceinline__ uint32_t bpack(__nv_bfloat16 a, __nv_bfloat16 b) {
    __nv_bfloat162 t(a, b);
    return *reinterpret_cast<uint32_t*>(&t);
}

__device__ __forceinline__ void copy_chunk(uint32_t sb, const __nv_bfloat16* Wg, int ch, int tid) {
    uint32_t dst = sb + SM_W + (ch & 1) * CHUNK_B;
    const char* src = (const char*)(Wg + (size_t)ch * CHUNK_E);
    #pragma unroll
    for (int t = 0; t < 10; t++) {
        int line = tid + t * 256;
        cp16(dst + line * 16, src + line * 16);
    }
}

// One 256 x (ntiles*16) x 256 GEMM, 3-pass hi/lo split, fragment-reusing.
// Caller must have issued copy_chunk(Wg, 0) + commit_group.
__device__ void gemm_run(char* smc, uint32_t sb, const __nv_bfloat16* Wg,
                         float acc[4][4][2][4], int tid, int wd, int wp, int lane,
                         int ntiles)
{
    const int l15 = lane & 15, l16 = (lane >> 4) * 8;
    #pragma unroll 1
    for (int kc = 0; kc < NCHUNK; kc++) {
        if (kc + 1 < NCHUNK) copy_chunk(sb, Wg, kc + 1, tid);
        asm volatile("cp.async.commit_group;" ::: "memory");
        asm volatile("cp.async.wait_group 1;" ::: "memory");
        __syncthreads();

        const uint32_t wb = sb + SM_W + (kc & 1) * CHUNK_B;
        #pragma unroll
        for (int ks = 0; ks < 2; ks++) {
            const int ka = ks * 16;
            const int kb = kc * 32 + ks * 16;

            uint32_t ah[4][4], al[4][4];
            #pragma unroll
            for (int i = 0; i < 4; i++) {
                uint32_t ro = (uint32_t)((wd * 64 + i * 16 + l15) * WPITCH + ka + l16) * 2;
                ldsm_x4(ah[i], wb + ro);
                ldsm_x4(al[i], wb + 20480 + ro);
            }

            #pragma unroll
            for (int s = 0; s < 4; s++) {
                int tt = 2 * s + wp;
                if (tt >= ntiles) break;
                int px = tt * 16;
                uint32_t bo = (uint32_t)((kb + l15) * BPITCH + px + l16) * 2;
                uint32_t bh[4], bl[4];
                ldsm_x4_t(bh, sb + SM_BH + bo);
                ldsm_x4_t(bl, sb + SM_BL + bo);
                #pragma unroll
                for (int i = 0; i < 4; i++)
                    #pragma unroll
                    for (int jl = 0; jl < 2; jl++) {
                        mma_16816(acc[i][s][jl], ah[i], &bh[jl * 2]);
                        mma_16816(acc[i][s][jl], ah[i], &bl[jl * 2]);
                        mma_16816(acc[i][s][jl], al[i], &bh[jl * 2]);
                    }
            }
        }
        __syncthreads();   // protect ping-pong buffer before next prefetch
    }
}

// ---------------- main fused masked-MLP kernel ----------------
extern "C" __global__ void __launch_bounds__(256, 1)
mlp_mma_kernel(const float* __restrict__ x,
               const void* __restrict__ mask,
               const float* __restrict__ b1g,
               const float* __restrict__ b2g,
               float* __restrict__ out)
{
    extern __shared__ char smc[];
    const uint32_t sb = (uint32_t)__cvta_generic_to_shared(smc);
    int* flg = (int*)(smc + SM_FLG);
    short* pos4 = (short*)(smc + SM_POS4);
    short* idx  = (short*)(smc + SM_IDX);

    const int tid = threadIdx.x, lane = tid & 31, wid = tid >> 5;
    const int wd = wid >> 1, wp = wid & 1;
    const int g = lane >> 2, tc = lane & 3;
    const int b = blockIdx.x >> 7, p0 = (blockIdx.x & 127) * 128;
    const float* xb = x + (size_t)b * 256 * HW + p0;
    const int gi0 = b * HW + p0;

    // ---- per-CTA mask dtype detection (32 words cover this tile under all encodings) ----
    if (tid < 32) {
        unsigned w = ((const unsigned*)mask)[gi0 / 4 + tid];
        bool fl = (w == 0x3F800000u);
        bool by = (w > 1u) && !fl;
        unsigned bb = __ballot_sync(0xFFFFFFFFu, by);
        if (tid == 0) flg[0] = bb ? 1 : 0;    // 1 = packed uint8, 0 = 4-byte (int32/float32)
    }
    __syncthreads();

    if (tid < 128) {
        int mv;
        if (flg[0]) mv = (((const unsigned char*)mask)[gi0 + tid] != 0);
        else        mv = (((const int*)mask)[gi0 + tid] != 0);
        smc[SM_MSK + tid] = (char)mv;
    }
    __syncthreads();

    // ---- warp 0: prefix scan -> pos4 / idx / nc ----
    if (wid == 0) {
        int base = lane * 4;
        int m0 = smc[SM_MSK + base], m1 = smc[SM_MSK + base + 1];
        int m2 = smc[SM_MSK + base + 2], m3 = smc[SM_MSK + base + 3];
        int c = m0 + m1 + m2 + m3;
        int sc = c;
        #pragma unroll
        for (int o = 1; o < 32; o <<= 1) {
            int t = __shfl_up_sync(0xFFFFFFFFu, sc, o);
            if (lane >= o) sc += t;
        }
        int run = sc - c;
        pos4[lane] = (short)run;
        if (m0) idx[run++] = (short)(base);
        if (m1) idx[run++] = (short)(base + 1);
        if (m2) idx[run++] = (short)(base + 2);
        if (m3) idx[run++] = (short)(base + 3);
        if (lane == 31) flg[1] = run;   // nc
    }

    // ---- prefetch W1 chunk 0 while loading X ----
    copy_chunk(sb, g_W1s, 0, tid);
    asm volatile("cp.async.commit_group;" ::: "memory");
    __syncthreads();
    const int nc = flg[1];
    const int ntiles = (nc + 15) >> 4;

    // ---- X load + hi/lo split + compacted store ----
    __nv_bfloat16* Bh = (__nv_bfloat16*)(smc + SM_BH);
    __nv_bfloat16* Bl = (__nv_bfloat16*)(smc + SM_BL);
    #pragma unroll 4
    for (int it = 0; it < 32; it++) {
        int e = tid + it * 256;          // 0..8191 float4s
        int c = e >> 5;                  // channel
        int q = (e & 31) * 4;            // pixel base
        float4 v = *(const float4*)(xb + (size_t)c * HW + q);
        int cnt = pos4[q >> 2];
        float vv[4] = {v.x, v.y, v.z, v.w};
        #pragma unroll
        for (int i = 0; i < 4; i++) {
            if (smc[SM_MSK + q + i]) {
                __nv_bfloat16 h = __float2bfloat16(vv[i]);
                Bh[c * BPITCH + cnt] = h;
                Bl[c * BPITCH + cnt] = __float2bfloat16(vv[i] - __bfloat162float(h));
                cnt++;
            }
        }
    }
    // gemm_run's first wait+sync orders these stores before compute

    float acc[4][4][2][4];
    #pragma unroll
    for (int i = 0; i < 4; i++)
        #pragma unroll
        for (int s = 0; s < 4; s++)
            #pragma unroll
            for (int jl = 0; jl < 2; jl++)
                #pragma unroll
                for (int r = 0; r < 4; r++) acc[i][s][jl][r] = 0.f;

    // ---- GEMM1: H = relu(W1T @ Xc + b1) ----
    gemm_run(smc, sb, g_W1s, acc, tid, wd, wp, lane, ntiles);

    // prefetch W2 chunk 0, then H epilogue (overlap)
    copy_chunk(sb, g_W2s, 0, tid);
    asm volatile("cp.async.commit_group;" ::: "memory");

    #pragma unroll
    for (int i = 0; i < 4; i++) {
        int r0 = wd * 64 + i * 16 + g;
        float bv0 = b1g[r0], bv1 = b1g[r0 + 8];
        #pragma unroll
        for (int s = 0; s < 4; s++) {
            int tt = 2 * s + wp;
            if (tt >= ntiles) break;
            #pragma unroll
            for (int jl = 0; jl < 2; jl++) {
                int px = tt * 16 + jl * 8 + tc * 2;
                float h00 = fmaxf(acc[i][s][jl][0] + bv0, 0.f);
                float h01 = fmaxf(acc[i][s][jl][1] + bv0, 0.f);
                float h10 = fmaxf(acc[i][s][jl][2] + bv1, 0.f);
                float h11 = fmaxf(acc[i][s][jl][3] + bv1, 0.f);
                __nv_bfloat16 a0 = __float2bfloat16(h00), a1 = __float2bfloat16(h01);
                __nv_bfloat16 c0 = __float2bfloat16(h10), c1 = __float2bfloat16(h11);
                *(uint32_t*)&Bh[r0 * BPITCH + px] = bpack(a0, a1);
                *(uint32_t*)&Bl[r0 * BPITCH + px] =
                    bpack(__float2bfloat16(h00 - __bfloat162float(a0)),
                          __float2bfloat16(h01 - __bfloat162float(a1)));
                *(uint32_t*)&Bh[(r0 + 8) * BPITCH + px] = bpack(c0, c1);
                *(uint32_t*)&Bl[(r0 + 8) * BPITCH + px] =
                    bpack(__float2bfloat16(h10 - __bfloat162float(c0)),
                          __float2bfloat16(h11 - __bfloat162float(c1)));
                #pragma unroll
                for (int r = 0; r < 4; r++) acc[i][s][jl][r] = 0.f;
            }
        }
    }

    // ---- GEMM2: Y = W2T @ Hc + b2 ----
    gemm_run(smc, sb, g_W2s, acc, tid, wd, wp, lane, ntiles);

    // ---- Y scatter (masked pixels) ----
    float* ob = out + (size_t)b * 256 * HW + p0;
    #pragma unroll
    for (int i = 0; i < 4; i++) {
        int r0 = wd * 64 + i * 16 + g;
        float bv0 = b2g[r0], bv1 = b2g[r0 + 8];
        #pragma unroll
        for (int s = 0; s < 4; s++) {
            int tt = 2 * s + wp;
            if (tt >= ntiles) break;
            #pragma unroll
            for (int jl = 0; jl < 2; jl++) {
                int pc = tt * 16 + jl * 8 + tc * 2;
                if (pc < nc) {
                    int p = idx[pc];
                    ob[(size_t)r0 * HW + p]       = acc[i][s][jl][0] + bv0;
                    ob[(size_t)(r0 + 8) * HW + p] = acc[i][s][jl][2] + bv1;
                }
                if (pc + 1 < nc) {
                    int p = idx[pc + 1];
                    ob[(size_t)r0 * HW + p]       = acc[i][s][jl][1] + bv0;
                    ob[(size_t)(r0 + 8) * HW + p] = acc[i][s][jl][3] + bv1;
                }
            }
        }
    }

    // ---- identity copy (unmasked pixels), coalesced float2 ----
    #pragma unroll 4
    for (int it = 0; it < 64; it++) {
        int e2 = tid + it * 256;         // float2 index, 16384 total
        int c = e2 >> 6;
        int q = (e2 & 63) * 2;
        int m0 = smc[SM_MSK + q], m1 = smc[SM_MSK + q + 1];
        if (m0 & m1) continue;
        float2 v = *(const float2*)(xb + (size_t)c * HW + q);
        if (!m0) ob[(size_t)c * HW + q]     = v.x;
        if (!m1) ob[(size_t)c * HW + q + 1] = v.y;
    }
}

extern "C" void kernel_launch(void* const* d_in, const int* in_sizes, int n_in,
                              void* d_out, int out_size)
{
    const float* x    = (const float*)d_in[0];
    const void*  mask = d_in[1];
    const float* W1   = (const float*)d_in[2];
    const float* b1   = (const float*)d_in[3];
    const float* W2   = (const float*)d_in[4];
    const float* b2   = (const float*)d_in[5];
    float*       out  = (float*)d_out;

    prep_weights_kernel<<<256, 256>>>(W1, W2);

    cudaFuncSetAttribute(mlp_mma_kernel,
                         cudaFuncAttributeMaxDynamicSharedMemorySize, SM_TOTAL);
    mlp_mma_kernel<<<2048, 256, SM_TOTAL>>>(x, mask, b1, b2, out);
}

// round 7
// speedup vs baseline: 2.9285x; 1.1589x over previous
#include <cuda_runtime.h>
#include <cuda_bf16.h>
#include <cstdint>

#define HW 16384
#define NTH 512       // 16 warps
#define BPITCH 136    // B smem pitch (bf16): 256 ch rows x up to 128 px
#define WPITCH 40     // W smem pitch (bf16) per 32-k chunk
#define NCHUNK 8      // 8 chunks of k=32
#define CHUNK_B 40960 // bytes per chunk (hi 20480 + lo 20480)
#define CHUNK_E 20480 // bf16 elems per chunk

// ---- smem layout (bytes) ----
#define SM_BH   0
#define SM_BL   69632
#define SM_W    139264            // 2 x 40960 ping-pong
#define SM_MSK  221184
#define SM_POS4 221312            // 32 x int16
#define SM_IDX  221440            // 128 x int16
#define SM_FLG  221696
#define SM_TOTAL 221824

__device__ __align__(16) __nv_bfloat16 g_W1s[NCHUNK * CHUNK_E];
__device__ __align__(16) __nv_bfloat16 g_W2s[NCHUNK * CHUNK_E];

// ---------------- weight prep: transpose + hi/lo split + chunked layout ----------------
extern "C" __global__ void prep_weights_kernel(const float* __restrict__ W1,
                                               const float* __restrict__ W2)
{
    int k = blockIdx.x;      // input channel (K dim of WT)
    int m = threadIdx.x;     // output channel
    int ch = k >> 5, kk = k & 31;
    int hi_off = ch * CHUNK_E + m * WPITCH + kk;

    float w1 = W1[k * 256 + m];
    __nv_bfloat16 h1 = __float2bfloat16(w1);
    g_W1s[hi_off]         = h1;
    g_W1s[hi_off + 10240] = __float2bfloat16(w1 - __bfloat162float(h1));

    float w2 = W2[k * 256 + m];
    __nv_bfloat16 h2 = __float2bfloat16(w2);
    g_W2s[hi_off]         = h2;
    g_W2s[hi_off + 10240] = __float2bfloat16(w2 - __bfloat162float(h2));
}

// ---------------- helpers ----------------
__device__ __forceinline__ void ldsm_x4(uint32_t* r, uint32_t addr) {
    asm volatile("ldmatrix.sync.aligned.m8n8.x4.shared.b16 {%0,%1,%2,%3}, [%4];"
                 : "=r"(r[0]), "=r"(r[1]), "=r"(r[2]), "=r"(r[3]) : "r"(addr));
}
__device__ __forceinline__ void ldsm_x4_t(uint32_t* r, uint32_t addr) {
    asm volatile("ldmatrix.sync.aligned.m8n8.x4.trans.shared.b16 {%0,%1,%2,%3}, [%4];"
                 : "=r"(r[0]), "=r"(r[1]), "=r"(r[2]), "=r"(r[3]) : "r"(addr));
}
__device__ __forceinline__ void mma_16816(float* d, const uint32_t* a, const uint32_t* b) {
    asm volatile("mma.sync.aligned.m16n8k16.row.col.f32.bf16.bf16.f32 "
                 "{%0,%1,%2,%3}, {%4,%5,%6,%7}, {%8,%9}, {%0,%1,%2,%3};"
                 : "+f"(d[0]), "+f"(d[1]), "+f"(d[2]), "+f"(d[3])
                 : "r"(a[0]), "r"(a[1]), "r"(a[2]), "r"(a[3]), "r"(b[0]), "r"(b[1]));
}
__device__ __forceinline__ void cp16(uint32_t dst, const void* src) {
    asm volatile("cp.async.cg.shared.global [%0], [%1], 16;" :: "r"(dst), "l"(src));
}
__device__ __forceinline__ uint32_t bpack(__nv_bfloat16 a, __nv_bfloat16 b) {
    __nv_bfloat162 t(a, b);
    return *reinterpret_cast<uint32_t*>(&t);
}
__device__ __forceinline__ void copy_chunk(uint32_t sb, const __nv_bfloat16* Wg, int ch, int tid) {
    uint32_t dst = sb + SM_W + (ch & 1) * CHUNK_B;
    const char* src = (const char*)(Wg + (size_t)ch * CHUNK_E);
    #pragma unroll
    for (int t = 0; t < 5; t++) {
        int line = tid + t * NTH;
        cp16(dst + line * 16, src + line * 16);
    }
}

// One 256 x (ntiles*16) x 256 GEMM, 3-pass hi/lo split.
// M split 8 ways over warps (wd), pixels split 2 ways (wp).
// Caller must have issued copy_chunk(Wg,0) + commit_group.
__device__ void gemm_run(uint32_t sb, const __nv_bfloat16* Wg,
                         float acc[2][4][2][4], int tid, int wd, int wp, int lane,
                         int ntiles)
{
    const int l15 = lane & 15, l16 = (lane >> 4) * 8;
    #pragma unroll 1
    for (int kc = 0; kc < NCHUNK; kc++) {
        if (kc + 1 < NCHUNK) copy_chunk(sb, Wg, kc + 1, tid);
        asm volatile("cp.async.commit_group;" ::: "memory");
        asm volatile("cp.async.wait_group 1;" ::: "memory");
        __syncthreads();

        const uint32_t wb = sb + SM_W + (kc & 1) * CHUNK_B;
        #pragma unroll
        for (int ks = 0; ks < 2; ks++) {
            const int ka = ks * 16;
            const int kb = kc * 32 + ks * 16;

            uint32_t ah[2][4], al[2][4];
            #pragma unroll
            for (int i = 0; i < 2; i++) {
                uint32_t ro = (uint32_t)((wd * 32 + i * 16 + l15) * WPITCH + ka + l16) * 2;
                ldsm_x4(ah[i], wb + ro);
                ldsm_x4(al[i], wb + 20480 + ro);
            }

            #pragma unroll
            for (int s = 0; s < 4; s++) {
                int tt = 2 * s + wp;
                if (tt >= ntiles) break;
                uint32_t bo = (uint32_t)((kb + l15) * BPITCH + tt * 16 + l16) * 2;
                uint32_t bh[4], bl[4];
                ldsm_x4_t(bh, sb + SM_BH + bo);
                ldsm_x4_t(bl, sb + SM_BL + bo);
                // pass-outer: 4 independent MMAs between accumulator reuses
                #pragma unroll
                for (int pass = 0; pass < 3; pass++) {
                    const uint32_t* av0 = (pass == 2) ? al[0] : ah[0];
                    const uint32_t* av1 = (pass == 2) ? al[1] : ah[1];
                    const uint32_t* bv  = (pass == 1) ? bl : bh;
                    mma_16816(acc[0][s][0], av0, &bv[0]);
                    mma_16816(acc[1][s][0], av1, &bv[0]);
                    mma_16816(acc[0][s][1], av0, &bv[2]);
                    mma_16816(acc[1][s][1], av1, &bv[2]);
                }
            }
        }
        __syncthreads();   // protect ping-pong buffer before next prefetch
    }
}

// ---------------- main fused masked-MLP kernel ----------------
extern "C" __global__ void __launch_bounds__(NTH, 1)
mlp_mma_kernel(const float* __restrict__ x,
               const void* __restrict__ mask,
               const float* __restrict__ b1g,
               const float* __restrict__ b2g,
               float* __restrict__ out)
{
    extern __shared__ char smc[];
    const uint32_t sb = (uint32_t)__cvta_generic_to_shared(smc);
    int* flg = (int*)(smc + SM_FLG);
    short* pos4 = (short*)(smc + SM_POS4);
    short* idx  = (short*)(smc + SM_IDX);

    const int tid = threadIdx.x, lane = tid & 31, wid = tid >> 5;
    const int wd = wid >> 1, wp = wid & 1;       // wd 0..7 (32 M rows), wp 0..1
    const int g = lane >> 2, tc = lane & 3;
    const int b = blockIdx.x >> 7, p0 = (blockIdx.x & 127) * 128;
    const float* xb = x + (size_t)b * 256 * HW + p0;
    const int gi0 = b * HW + p0;

    // ---- per-CTA mask dtype detection ----
    if (tid < 32) {
        unsigned w = ((const unsigned*)mask)[gi0 / 4 + tid];
        bool fl = (w == 0x3F800000u);
        bool by = (w > 1u) && !fl;
        unsigned bb = __ballot_sync(0xFFFFFFFFu, by);
        if (tid == 0) flg[0] = bb ? 1 : 0;
    }
    __syncthreads();

    if (tid < 128) {
        int mv;
        if (flg[0]) mv = (((const unsigned char*)mask)[gi0 + tid] != 0);
        else        mv = (((const int*)mask)[gi0 + tid] != 0);
        smc[SM_MSK + tid] = (char)mv;
    }
    __syncthreads();

    // ---- warp 0: prefix scan -> pos4 / idx / nc ----
    if (wid == 0) {
        int base = lane * 4;
        int m0 = smc[SM_MSK + base], m1 = smc[SM_MSK + base + 1];
        int m2 = smc[SM_MSK + base + 2], m3 = smc[SM_MSK + base + 3];
        int c = m0 + m1 + m2 + m3;
        int sc = c;
        #pragma unroll
        for (int o = 1; o < 32; o <<= 1) {
            int t = __shfl_up_sync(0xFFFFFFFFu, sc, o);
            if (lane >= o) sc += t;
        }
        int run = sc - c;
        pos4[lane] = (short)run;
        if (m0) idx[run++] = (short)(base);
        if (m1) idx[run++] = (short)(base + 1);
        if (m2) idx[run++] = (short)(base + 2);
        if (m3) idx[run++] = (short)(base + 3);
        if (lane == 31) flg[1] = run;
    }

    // ---- prefetch W1 chunk 0 while loading X ----
    copy_chunk(sb, g_W1s, 0, tid);
    asm volatile("cp.async.commit_group;" ::: "memory");
    __syncthreads();
    const int nc = flg[1];
    const int ntiles = (nc + 15) >> 4;

    // ---- X load + hi/lo split + compacted store ----
    __nv_bfloat16* Bh = (__nv_bfloat16*)(smc + SM_BH);
    __nv_bfloat16* Bl = (__nv_bfloat16*)(smc + SM_BL);
    #pragma unroll 4
    for (int it = 0; it < 16; it++) {
        int e = tid + it * NTH;          // 0..8191 float4s
        int c = e >> 5;
        int q = (e & 31) * 4;
        float4 v = *(const float4*)(xb + (size_t)c * HW + q);
        int cnt = pos4[q >> 2];
        float vv[4] = {v.x, v.y, v.z, v.w};
        #pragma unroll
        for (int i = 0; i < 4; i++) {
            if (smc[SM_MSK + q + i]) {
                __nv_bfloat16 h = __float2bfloat16(vv[i]);
                Bh[c * BPITCH + cnt] = h;
                Bl[c * BPITCH + cnt] = __float2bfloat16(vv[i] - __bfloat162float(h));
                cnt++;
            }
        }
    }
    // gemm_run's first wait+sync orders these stores before compute

    float acc[2][4][2][4];
    #pragma unroll
    for (int i = 0; i < 2; i++)
        #pragma unroll
        for (int s = 0; s < 4; s++)
            #pragma unroll
            for (int jl = 0; jl < 2; jl++)
                #pragma unroll
                for (int r = 0; r < 4; r++) acc[i][s][jl][r] = 0.f;

    // ---- GEMM1: H = relu(W1T @ Xc + b1) ----
    gemm_run(sb, g_W1s, acc, tid, wd, wp, lane, ntiles);

    // prefetch W2 chunk 0, overlap with H epilogue
    copy_chunk(sb, g_W2s, 0, tid);
    asm volatile("cp.async.commit_group;" ::: "memory");

    #pragma unroll
    for (int i = 0; i < 2; i++) {
        int r0 = wd * 32 + i * 16 + g;
        float bv0 = b1g[r0], bv1 = b1g[r0 + 8];
        #pragma unroll
        for (int s = 0; s < 4; s++) {
            int tt = 2 * s + wp;
            if (tt >= ntiles) break;
            #pragma unroll
            for (int jl = 0; jl < 2; jl++) {
                int px = tt * 16 + jl * 8 + tc * 2;
                float h00 = fmaxf(acc[i][s][jl][0] + bv0, 0.f);
                float h01 = fmaxf(acc[i][s][jl][1] + bv0, 0.f);
                float h10 = fmaxf(acc[i][s][jl][2] + bv1, 0.f);
                float h11 = fmaxf(acc[i][s][jl][3] + bv1, 0.f);
                __nv_bfloat16 a0 = __float2bfloat16(h00), a1 = __float2bfloat16(h01);
                __nv_bfloat16 c0 = __float2bfloat16(h10), c1 = __float2bfloat16(h11);
                *(uint32_t*)&Bh[r0 * BPITCH + px] = bpack(a0, a1);
                *(uint32_t*)&Bl[r0 * BPITCH + px] =
                    bpack(__float2bfloat16(h00 - __bfloat162float(a0)),
                          __float2bfloat16(h01 - __bfloat162float(a1)));
                *(uint32_t*)&Bh[(r0 + 8) * BPITCH + px] = bpack(c0, c1);
                *(uint32_t*)&Bl[(r0 + 8) * BPITCH + px] =
                    bpack(__float2bfloat16(h10 - __bfloat162float(c0)),
                          __float2bfloat16(h11 - __bfloat162float(c1)));
                #pragma unroll
                for (int r = 0; r < 4; r++) acc[i][s][jl][r] = 0.f;
            }
        }
    }

    // ---- GEMM2: Y = W2T @ Hc + b2 ----
    gemm_run(sb, g_W2s, acc, tid, wd, wp, lane, ntiles);

    // ---- Y scatter (masked pixels) ----
    float* ob = out + (size_t)b * 256 * HW + p0;
    #pragma unroll
    for (int i = 0; i < 2; i++) {
        int r0 = wd * 32 + i * 16 + g;
        float bv0 = b2g[r0], bv1 = b2g[r0 + 8];
        #pragma unroll
        for (int s = 0; s < 4; s++) {
            int tt = 2 * s + wp;
            if (tt >= ntiles) break;
            #pragma unroll
            for (int jl = 0; jl < 2; jl++) {
                int pc = tt * 16 + jl * 8 + tc * 2;
                if (pc < nc) {
                    int p = idx[pc];
                    ob[(size_t)r0 * HW + p]       = acc[i][s][jl][0] + bv0;
                    ob[(size_t)(r0 + 8) * HW + p] = acc[i][s][jl][2] + bv1;
                }
                if (pc + 1 < nc) {
                    int p = idx[pc + 1];
                    ob[(size_t)r0 * HW + p]       = acc[i][s][jl][1] + bv0;
                    ob[(size_t)(r0 + 8) * HW + p] = acc[i][s][jl][3] + bv1;
                }
            }
        }
    }

    // ---- identity copy (unmasked pixels) ----
    #pragma unroll 4
    for (int it = 0; it < 32; it++) {
        int e2 = tid + it * NTH;         // float2 index
        int c = e2 >> 6;
        int q = (e2 & 63) * 2;
        int m0 = smc[SM_MSK + q], m1 = smc[SM_MSK + q + 1];
        if (m0 & m1) continue;
        float2 v = *(const float2*)(xb + (size_t)c * HW + q);
        if (!m0) ob[(size_t)c * HW + q]     = v.x;
        if (!m1) ob[(size_t)c * HW + q + 1] = v.y;
    }
}

extern "C" void kernel_launch(void* const* d_in, const int* in_sizes, int n_in,
                              void* d_out, int out_size)
{
    const float* x    = (const float*)d_in[0];
    const void*  mask = d_in[1];
    const float* W1   = (const float*)d_in[2];
    const float* b1   = (const float*)d_in[3];
    const float* W2   = (const float*)d_in[4];
    const float* b2   = (const float*)d_in[5];
    float*       out  = (float*)d_out;

    prep_weights_kernel<<<256, 256>>>(W1, W2);

    cudaFuncSetAttribute(mlp_mma_kernel,
                         cudaFuncAttributeMaxDynamicSharedMemorySize, SM_TOTAL);
    mlp_mma_kernel<<<2048, NTH, SM_TOTAL>>>(x, mask, b1, b2, out);
}